// round 15
// baseline (speedup 1.0000x reference)
#include <cuda_runtime.h>
#include <cstdint>

#define B  64
#define C  512
#define S  768
#define K  128
#define KN 256
#define A  200
#define H  1024

#define NBLK 256
#define NTHR 256
#define KSPLIT 16
#define SCHUNK (S / KSPLIT)   // 48

#define STAGE_BYTES 12288     // 4 rows x 3072 B
#define NSTAGE 32             // 128 rows / 4

// Scratch (device globals — no allocation allowed)
__device__ float g_xmp[4 * B * S];        // x-sum partials (4 c-quarters) [cq][b][s]
__device__ float g_fcp[KSPLIT * H * B];   // fc partials [ks][h][b]

// Grid-wide sense-reversing barrier (flat single atomic counter — measured
// faster than flag polling (R7), ticket stealing (R9), and 2-level tree (R13)).
__device__ int          g_bar_count = 0;
__device__ volatile int g_bar_sense = 0;

__device__ __forceinline__ void grid_barrier(int& ls) {
    __syncthreads();
    if (threadIdx.x == 0) {
        const int target = ls ^ 1;
        ls = target;
        __threadfence();
        if (atomicAdd(&g_bar_count, 1) == NBLK - 1) {
            atomicExch(&g_bar_count, 0);
            __threadfence();
            g_bar_sense = target;
        } else {
            while (g_bar_sense != target) { }
        }
        __threadfence();
    } else {
        ls ^= 1;
    }
    __syncthreads();
}

__device__ __forceinline__ void f4add(float4& a, const float4 v) {
    a.x += v.x; a.y += v.y; a.z += v.z; a.w += v.w;
}

// L2-only prefetch for phase-2 W_t (R14: neutral but harmless).
__device__ __forceinline__ void prefetch_l2(const void* p) {
    asm volatile("prefetch.global.L2 [%0];" :: "l"(p));
}

// ---- bulk-async helpers ----------------------------------------------------
__device__ __forceinline__ uint32_t smem_u32(const void* p) {
    uint32_t a;
    asm("{ .reg .u64 t; cvta.to.shared.u64 t, %1; cvt.u32.u64 %0, t; }"
        : "=r"(a) : "l"(p));
    return a;
}
__device__ __forceinline__ void mbar_init(uint32_t mbar, uint32_t cnt) {
    asm volatile("mbarrier.init.shared.b64 [%0], %1;" :: "r"(mbar), "r"(cnt) : "memory");
}
__device__ __forceinline__ void mbar_inval(uint32_t mbar) {
    asm volatile("mbarrier.inval.shared.b64 [%0];" :: "r"(mbar) : "memory");
}
__device__ __forceinline__ void mbar_expect_tx(uint32_t mbar, uint32_t bytes) {
    asm volatile("mbarrier.arrive.expect_tx.shared.b64 _, [%0], %1;"
                 :: "r"(mbar), "r"(bytes) : "memory");
}
__device__ __forceinline__ void mbar_wait(uint32_t mbar, uint32_t parity) {
    uint32_t done;
    asm volatile(
        "{\n\t.reg .pred p;\n\t"
        "mbarrier.try_wait.parity.acquire.cta.shared::cta.b64 p, [%1], %2;\n\t"
        "selp.b32 %0, 1, 0, p;\n\t}"
        : "=r"(done) : "r"(mbar), "r"(parity) : "memory");
    if (!done) {
        asm volatile(
            "{\n\t.reg .pred P1;\n\t"
            "WL_%=:\n\t"
            "mbarrier.try_wait.parity.acquire.cta.shared::cta.b64 P1, [%0], %1, 0x989680;\n\t"
            "@P1 bra.uni WD_%=;\n\t"
            "bra.uni WL_%=;\n\t"
            "WD_%=:\n\t}"
            :: "r"(mbar), "r"(parity) : "memory");
    }
}
// 1D bulk copy global -> shared::cta, completion via mbarrier complete_tx.
__device__ __forceinline__ void bulk_g2s(uint32_t dst_smem, const void* gsrc,
                                         uint32_t bytes, uint32_t mbar) {
    asm volatile(
        "cp.async.bulk.shared::cta.global.mbarrier::complete_tx::bytes "
        "[%0], [%1], %2, [%3];"
        :: "r"(dst_smem), "l"(gsrc), "r"(bytes), "r"(mbar) : "memory");
}

__global__ void __launch_bounds__(NTHR, 2)
ham_persistent(const float* __restrict__ x,
               const float* __restrict__ W_t,
               const float* __restrict__ b_t,
               const float* __restrict__ gamma,
               const float* __restrict__ beta,
               const float* __restrict__ W_l,
               const float* __restrict__ b_l,
               const float* __restrict__ G_h,
               float* __restrict__ out_score,
               float* __restrict__ out_fc,
               float* __restrict__ out_omega) {
    // Phase 1: 2 x 12KB stage buffers + 2 mbarriers.
    // Phases 2-5 alias the same storage as a float array (17.4 KB needed).
    __shared__ __align__(1024) char smraw[2 * STAGE_BYTES + 64];
    float* sm = reinterpret_cast<float*>(smraw);

    const int blk = blockIdx.x;
    const int tid = threadIdx.x;
    int ls = g_bar_sense;                      // replay-safe sense init

    // ---- W_t L2 prefetch for phase 2 (1-2 inst per thread, no regs held).
    {
        const int h0  = (blk >> 4) * 64;
        const int s0  = (blk & 15) * SCHUNK;
        const int hh  = tid >> 2;              // 0..63
        const int q   = tid & 3;
        const int seg = q >> 1;
        const int sec = q & 1;
        prefetch_l2(W_t + (size_t)(h0 + hh) * (2 * S) + seg * S + s0 + sec * 32);
    }

    // ---------------- Phase 1: x-sum partials via cp.async.bulk ------------
    // block = (cq, b): rows c0..c0+127 of x[b] form ONE contiguous 393KB
    // span. Stream it through 2 double-buffered 12KB smem stages (bulk-async
    // engine bypasses the per-warp LDG/L1tex wavefront path); 192 threads
    // accumulate 4 rows/stage from smem (column t) into one register float4.
    {
        const int cq = blk >> 6;               // 0..3
        const int b  = blk & 63;
        const char* gsrc = reinterpret_cast<const char*>(x)
                         + ((size_t)b * C + cq * 128) * S * 4;

        const uint32_t smem_base = smem_u32(smraw);
        const uint32_t mbar0 = smem_base + 2 * STAGE_BYTES;
        const uint32_t mbar1 = mbar0 + 8;

        if (tid == 0) {
            mbar_init(mbar0, 1);
            mbar_init(mbar1, 1);
        }
        __syncthreads();
        asm volatile("fence.proxy.async.shared::cta;" ::: "memory");

        if (tid == 0) {
            mbar_expect_tx(mbar0, STAGE_BYTES);
            bulk_g2s(smem_base, gsrc, STAGE_BYTES, mbar0);
            mbar_expect_tx(mbar1, STAGE_BYTES);
            bulk_g2s(smem_base + STAGE_BYTES, gsrc + STAGE_BYTES, STAGE_BYTES, mbar1);
        }

        float4 acc = make_float4(0.f, 0.f, 0.f, 0.f);
        for (int s = 0; s < NSTAGE; ++s) {
            const int buf = s & 1;
            const uint32_t mb = buf ? mbar1 : mbar0;
            mbar_wait(mb, (s >> 1) & 1);
            if (tid < 192) {
                const char* bufp = smraw + buf * STAGE_BYTES;
#pragma unroll
                for (int r = 0; r < 4; ++r)
                    f4add(acc, *reinterpret_cast<const float4*>(
                                   bufp + r * 3072 + tid * 16));
            }
            __syncthreads();                   // buffer fully consumed
            if (tid == 0 && s + 2 < NSTAGE) {
                mbar_expect_tx(mb, STAGE_BYTES);
                bulk_g2s(smem_base + buf * STAGE_BYTES,
                         gsrc + (size_t)(s + 2) * STAGE_BYTES, STAGE_BYTES, mb);
            }
        }

        if (tid < 192)
            reinterpret_cast<float4*>(g_xmp)[(cq * B + b) * (S / 4) + tid] = acc;
        __syncthreads();
        if (tid == 0) { mbar_inval(mbar0); mbar_inval(mbar1); }
    }
    grid_barrier(ls);

    // ---------------- Phase 2: fc partial GEMM -----------------------------
    // fc[b,h] = sum_s x_mean[b,s] * (W_t[h,s] + 4*W_t[h,s+S]); x_mean built
    // on the fly from the 4 c-quarter partials (L2-resident).
    // 256 blocks = 16 h-tiles x 16 s-splits of 48; 4x4 register tile.
    {
        float (*Xs)[64] = reinterpret_cast<float(*)[64]>(sm);          // [sk][b]
        float (*Ws)[64] = reinterpret_cast<float(*)[64]>(sm + 1024);   // [sk][h]
        const int h0 = (blk >> 4) * 64;
        const int s0 = (blk & 15) * SCHUNK;
        const int tx = tid & 15;          // b group
        const int ty = tid >> 4;          // h group

        float acc[4][4] = {};             // [h][b]
        for (int sc = 0; sc < SCHUNK; sc += 16) {
            for (int i = tid; i < 1024; i += NTHR) {
                int hh = i >> 4, sk = i & 15;
                int s = s0 + sc + sk;
                const float* wr = W_t + (size_t)(h0 + hh) * (2 * S);
                Ws[sk][hh] = wr[s] + 4.0f * wr[s + S];
            }
            for (int i = tid; i < 1024; i += NTHR) {
                int bb = i >> 4, sk = i & 15;
                int idx = bb * S + s0 + sc + sk;
                float v = g_xmp[idx] + g_xmp[B * S + idx]
                        + g_xmp[2 * B * S + idx] + g_xmp[3 * B * S + idx];
                Xs[sk][bb] = v * (1.0f / C);
            }
            __syncthreads();
#pragma unroll
            for (int sk = 0; sk < 16; ++sk) {
                float a_[4], w_[4];
#pragma unroll
                for (int i = 0; i < 4; ++i) a_[i] = Ws[sk][ty * 4 + i];
#pragma unroll
                for (int j = 0; j < 4; ++j) w_[j] = Xs[sk][tx * 4 + j];
#pragma unroll
                for (int i = 0; i < 4; ++i)
#pragma unroll
                    for (int j = 0; j < 4; ++j)
                        acc[i][j] += a_[i] * w_[j];
            }
            __syncthreads();
        }
        float* dst = g_fcp + (size_t)(blk & 15) * (H * B);
#pragma unroll
        for (int i = 0; i < 4; ++i) {
            float4 v = make_float4(acc[i][0], acc[i][1], acc[i][2], acc[i][3]);
            *reinterpret_cast<float4*>(&dst[(h0 + ty * 4 + i) * B + tx * 4]) = v;
        }
    }
    grid_barrier(ls);

    // ---------------- Phase 3: BN (biased var over batch) + ReLU -----------
    // block handles 4 h columns x all 64 b; writes out_fc [b][h].
    {
        const int b    = tid & 63;
        const int hl   = tid >> 6;
        const int h    = blk * 4 + hl;
        const int wid  = tid >> 5;
        const int lane = tid & 31;

        float v = b_t[h];
#pragma unroll
        for (int ks = 0; ks < KSPLIT; ++ks)
            v += g_fcp[(size_t)ks * (H * B) + h * B + b];

        float s = v;
#pragma unroll
        for (int o = 16; o; o >>= 1) s += __shfl_down_sync(0xffffffffu, s, o);
        if (!lane) sm[wid] = s;
        __syncthreads();
        const float mean = (sm[hl * 2] + sm[hl * 2 + 1]) * (1.0f / B);

        const float d = v - mean;
        float s2 = d * d;
#pragma unroll
        for (int o = 16; o; o >>= 1) s2 += __shfl_down_sync(0xffffffffu, s2, o);
        if (!lane) sm[8 + wid] = s2;
        __syncthreads();
        const float var = (sm[8 + hl * 2] + sm[8 + hl * 2 + 1]) * (1.0f / B);

        out_fc[b * H + h] =
            fmaxf(d * rsqrtf(var + 1e-5f) * gamma[h] + beta[h], 0.0f);
    }
    grid_barrier(ls);

    // ---------------- Phase 4: score = sigmoid(relu_fc @ W_l^T + b_l) ------
    // block = (b-quad, k-octet): 16 x 16 = 256 blocks. W_l rows reused by 4 b.
    {
        const int b0 = (blk >> 4) * 4;
        const int k0 = (blk & 15) * 8;
        float4* r4 = reinterpret_cast<float4*>(sm);     // [4][256] float4

        for (int i = tid; i < 4 * (H / 4); i += NTHR)
            r4[i] = reinterpret_cast<const float4*>(out_fc)
                        [(b0 + (i >> 8)) * (H / 4) + (i & 255)];
        __syncthreads();

        const int w = tid >> 5, lane = tid & 31;
        const int k = k0 + w;
        const float4* wl4 = reinterpret_cast<const float4*>(W_l + (size_t)k * H);
        float acc0 = 0.f, acc1 = 0.f, acc2 = 0.f, acc3 = 0.f;
#pragma unroll
        for (int j = 0; j < 8; ++j) {
            const float4 wv = __ldg(wl4 + lane + 32 * j);
            const float4 a0 = r4[0 * 256 + lane + 32 * j];
            const float4 a1 = r4[1 * 256 + lane + 32 * j];
            const float4 a2 = r4[2 * 256 + lane + 32 * j];
            const float4 a3 = r4[3 * 256 + lane + 32 * j];
            acc0 += a0.x * wv.x + a0.y * wv.y + a0.z * wv.z + a0.w * wv.w;
            acc1 += a1.x * wv.x + a1.y * wv.y + a1.z * wv.z + a1.w * wv.w;
            acc2 += a2.x * wv.x + a2.y * wv.y + a2.z * wv.z + a2.w * wv.w;
            acc3 += a3.x * wv.x + a3.y * wv.y + a3.z * wv.z + a3.w * wv.w;
        }
#pragma unroll
        for (int o = 16; o; o >>= 1) {
            acc0 += __shfl_down_sync(0xffffffffu, acc0, o);
            acc1 += __shfl_down_sync(0xffffffffu, acc1, o);
            acc2 += __shfl_down_sync(0xffffffffu, acc2, o);
            acc3 += __shfl_down_sync(0xffffffffu, acc3, o);
        }
        if (!lane) {
            const float bl = b_l[k];
            out_score[(b0 + 0) * K + k] = 1.0f / (1.0f + expf(-(acc0 + bl)));
            out_score[(b0 + 1) * K + k] = 1.0f / (1.0f + expf(-(acc1 + bl)));
            out_score[(b0 + 2) * K + k] = 1.0f / (1.0f + expf(-(acc2 + bl)));
            out_score[(b0 + 3) * K + k] = 1.0f / (1.0f + expf(-(acc3 + bl)));
        }
    }
    grid_barrier(ls);

    // ---------------- Phase 5: Q = score @ G_h, omega broadcast ------------
    // block = (b, n-slice of 64): 64 x 4 = 256 blocks.
    {
        const int b  = blk >> 2;
        const int n0 = (blk & 3) * 64;
        float* scsh  = sm;          // [128] score
        float* qpart = sm + 128;    // [4][64]
        float* qv    = sm + 384;    // [64]

        if (tid < K) scsh[tid] = out_score[b * K + tid];  // plain load (ours)
        __syncthreads();

        const int kh = tid >> 6;    // 0..3 -> k range [kh*32, kh*32+32)
        const int n  = tid & 63;
        float acc = 0.f;
#pragma unroll 8
        for (int j = 0; j < 32; ++j) {
            const int k = kh * 32 + j;
            acc += scsh[k] * __ldg(G_h + k * KN + n0 + n);
        }
        qpart[kh * 64 + n] = acc;
        __syncthreads();
        if (tid < 64)
            qv[tid] = qpart[tid] + qpart[64 + tid]
                    + qpart[128 + tid] + qpart[192 + tid];
        __syncthreads();

        // write 64 n rows x 200 a = 3200 float4
        float4* po = reinterpret_cast<float4*>(
            out_omega + (size_t)b * KN * A + (size_t)n0 * A);
#pragma unroll
        for (int it = 0; it < 13; ++it) {
            const int i4 = it * NTHR + tid;
            if (i4 < 64 * (A / 4)) {
                const float v = qv[i4 / (A / 4)];
                po[i4] = make_float4(v, v, v, v);
            }
        }
    }
}

// ---------------------------------------------------------------------------
extern "C" void kernel_launch(void* const* d_in, const int* in_sizes, int n_in,
                              void* d_out, int out_size) {
    const float* x     = (const float*)d_in[0];
    // d_in[1] omega_h, d_in[2] W_s1, d_in[3] W_s2: mathematically dead
    const float* W_t   = (const float*)d_in[4];
    const float* b_t   = (const float*)d_in[5];
    const float* gamma = (const float*)d_in[6];
    const float* beta  = (const float*)d_in[7];
    const float* W_l   = (const float*)d_in[8];
    const float* b_l   = (const float*)d_in[9];
    const float* G_h   = (const float*)d_in[10];

    float* out       = (float*)d_out;
    float* out_score = out;                    // [B, K]
    float* out_fc    = out + B * K;            // [B, H]
    float* out_omega = out + B * K + B * H;    // [B, KN, A]

    ham_persistent<<<NBLK, NTHR>>>(x, W_t, b_t, gamma, beta, W_l, b_l, G_h,
                                   out_score, out_fc, out_omega);
}

// round 16
// speedup vs baseline: 1.0768x; 1.0768x over previous
#include <cuda_runtime.h>
#include <cstdint>

#define B  64
#define C  512
#define S  768
#define K  128
#define KN 256
#define A  200
#define H  1024

#define NBLK 256
#define NTHR 256
#define KSPLIT 16
#define SCHUNK (S / KSPLIT)   // 48

#define STAGE_BYTES 12288     // 4 rows x 3072 B
#define NSTAGE 32             // 128 rows / 4
#define NBUF 4
#define SMEM_TOTAL (NBUF * STAGE_BYTES + 64)   // 49216 B dynamic smem

// Scratch (device globals — no allocation allowed)
__device__ float g_xmp[4 * B * S];        // x-sum partials (4 c-quarters) [cq][b][s]
__device__ float g_fcp[KSPLIT * H * B];   // fc partials [ks][h][b]

// Grid-wide sense-reversing barrier (flat single atomic counter — measured
// faster than flag polling (R7), ticket stealing (R9), and 2-level tree (R13)).
__device__ int          g_bar_count = 0;
__device__ volatile int g_bar_sense = 0;

__device__ __forceinline__ void grid_barrier(int& ls) {
    __syncthreads();
    if (threadIdx.x == 0) {
        const int target = ls ^ 1;
        ls = target;
        __threadfence();
        if (atomicAdd(&g_bar_count, 1) == NBLK - 1) {
            atomicExch(&g_bar_count, 0);
            __threadfence();
            g_bar_sense = target;
        } else {
            while (g_bar_sense != target) { }
        }
        __threadfence();
    } else {
        ls ^= 1;
    }
    __syncthreads();
}

__device__ __forceinline__ void f4add(float4& a, const float4 v) {
    a.x += v.x; a.y += v.y; a.z += v.z; a.w += v.w;
}

// L2-only prefetch for phase-2 W_t (R14: neutral but harmless).
__device__ __forceinline__ void prefetch_l2(const void* p) {
    asm volatile("prefetch.global.L2 [%0];" :: "l"(p));
}

// ---- bulk-async helpers ----------------------------------------------------
__device__ __forceinline__ uint32_t smem_u32(const void* p) {
    uint32_t a;
    asm("{ .reg .u64 t; cvta.to.shared.u64 t, %1; cvt.u32.u64 %0, t; }"
        : "=r"(a) : "l"(p));
    return a;
}
__device__ __forceinline__ void mbar_init(uint32_t mbar, uint32_t cnt) {
    asm volatile("mbarrier.init.shared.b64 [%0], %1;" :: "r"(mbar), "r"(cnt) : "memory");
}
__device__ __forceinline__ void mbar_inval(uint32_t mbar) {
    asm volatile("mbarrier.inval.shared.b64 [%0];" :: "r"(mbar) : "memory");
}
__device__ __forceinline__ void mbar_expect_tx(uint32_t mbar, uint32_t bytes) {
    asm volatile("mbarrier.arrive.expect_tx.shared.b64 _, [%0], %1;"
                 :: "r"(mbar), "r"(bytes) : "memory");
}
__device__ __forceinline__ void mbar_wait(uint32_t mbar, uint32_t parity) {
    uint32_t done;
    asm volatile(
        "{\n\t.reg .pred p;\n\t"
        "mbarrier.try_wait.parity.acquire.cta.shared::cta.b64 p, [%1], %2;\n\t"
        "selp.b32 %0, 1, 0, p;\n\t}"
        : "=r"(done) : "r"(mbar), "r"(parity) : "memory");
    if (!done) {
        asm volatile(
            "{\n\t.reg .pred P1;\n\t"
            "WL_%=:\n\t"
            "mbarrier.try_wait.parity.acquire.cta.shared::cta.b64 P1, [%0], %1, 0x989680;\n\t"
            "@P1 bra.uni WD_%=;\n\t"
            "bra.uni WL_%=;\n\t"
            "WD_%=:\n\t}"
            :: "r"(mbar), "r"(parity) : "memory");
    }
}
// 1D bulk copy global -> shared::cta, completion via mbarrier complete_tx.
__device__ __forceinline__ void bulk_g2s(uint32_t dst_smem, const void* gsrc,
                                         uint32_t bytes, uint32_t mbar) {
    asm volatile(
        "cp.async.bulk.shared::cta.global.mbarrier::complete_tx::bytes "
        "[%0], [%1], %2, [%3];"
        :: "r"(dst_smem), "l"(gsrc), "r"(bytes), "r"(mbar) : "memory");
}

__global__ void __launch_bounds__(NTHR, 2)
ham_persistent(const float* __restrict__ x,
               const float* __restrict__ W_t,
               const float* __restrict__ b_t,
               const float* __restrict__ gamma,
               const float* __restrict__ beta,
               const float* __restrict__ W_l,
               const float* __restrict__ b_l,
               const float* __restrict__ G_h,
               float* __restrict__ out_score,
               float* __restrict__ out_fc,
               float* __restrict__ out_omega) {
    extern __shared__ __align__(1024) char smraw[];   // 4 stage bufs + mbars
    float* sm = reinterpret_cast<float*>(smraw);      // phases 2-5 alias buf 0..

    const int blk = blockIdx.x;
    const int tid = threadIdx.x;
    int ls = g_bar_sense;                      // replay-safe sense init

    // ---- W_t L2 prefetch for phase 2 (1-2 inst per thread, no regs held).
    {
        const int h0  = (blk >> 4) * 64;
        const int s0  = (blk & 15) * SCHUNK;
        const int hh  = tid >> 2;              // 0..63
        const int q   = tid & 3;
        const int seg = q >> 1;
        const int sec = q & 1;
        prefetch_l2(W_t + (size_t)(h0 + hh) * (2 * S) + seg * S + s0 + sec * 32);
    }

    // ---------------- Phase 1: x-sum partials via 4-deep cp.async.bulk -----
    // block = (cq, b): rows c0..c0+127 of x[b] = one contiguous 393KB span.
    // 4 x 12KB buffers; 3 copies outstanding (36KB/CTA, 72KB/SM in flight)
    // while the 4th is consumed. 192 threads accumulate 4 rows/stage from
    // smem (col t) into one register float4.
    {
        const int cq = blk >> 6;               // 0..3
        const int b  = blk & 63;
        const char* gsrc = reinterpret_cast<const char*>(x)
                         + ((size_t)b * C + cq * 128) * S * 4;

        const uint32_t smem_base = smem_u32(smraw);
        const uint32_t mbar_base = smem_base + NBUF * STAGE_BYTES;

        if (tid == 0) {
#pragma unroll
            for (int i = 0; i < NBUF; ++i) mbar_init(mbar_base + 8 * i, 1);
        }
        __syncthreads();
        asm volatile("fence.proxy.async.shared::cta;" ::: "memory");

        if (tid == 0) {
#pragma unroll
            for (int i = 0; i < NBUF; ++i) {
                mbar_expect_tx(mbar_base + 8 * i, STAGE_BYTES);
                bulk_g2s(smem_base + i * STAGE_BYTES,
                         gsrc + (size_t)i * STAGE_BYTES, STAGE_BYTES,
                         mbar_base + 8 * i);
            }
        }

        float4 acc = make_float4(0.f, 0.f, 0.f, 0.f);
        for (int s = 0; s < NSTAGE; ++s) {
            const int buf = s & (NBUF - 1);
            const uint32_t mb = mbar_base + 8 * buf;
            mbar_wait(mb, (s >> 2) & 1);
            if (tid < 192) {
                const char* bufp = smraw + buf * STAGE_BYTES;
#pragma unroll
                for (int r = 0; r < 4; ++r)
                    f4add(acc, *reinterpret_cast<const float4*>(
                                   bufp + r * 3072 + tid * 16));
            }
            __syncthreads();                   // buffer fully consumed
            if (tid == 0 && s + NBUF < NSTAGE) {
                mbar_expect_tx(mb, STAGE_BYTES);
                bulk_g2s(smem_base + buf * STAGE_BYTES,
                         gsrc + (size_t)(s + NBUF) * STAGE_BYTES, STAGE_BYTES, mb);
            }
        }

        if (tid < 192)
            reinterpret_cast<float4*>(g_xmp)[(cq * B + b) * (S / 4) + tid] = acc;
        __syncthreads();
        if (tid == 0) {
#pragma unroll
            for (int i = 0; i < NBUF; ++i) mbar_inval(mbar_base + 8 * i);
        }
    }
    grid_barrier(ls);

    // ---------------- Phase 2: fc partial GEMM -----------------------------
    // fc[b,h] = sum_s x_mean[b,s] * (W_t[h,s] + 4*W_t[h,s+S]); x_mean built
    // on the fly from the 4 c-quarter partials (L2-resident).
    // 256 blocks = 16 h-tiles x 16 s-splits of 48; 4x4 register tile.
    {
        float (*Xs)[64] = reinterpret_cast<float(*)[64]>(sm);          // [sk][b]
        float (*Ws)[64] = reinterpret_cast<float(*)[64]>(sm + 1024);   // [sk][h]
        const int h0 = (blk >> 4) * 64;
        const int s0 = (blk & 15) * SCHUNK;
        const int tx = tid & 15;          // b group
        const int ty = tid >> 4;          // h group

        float acc[4][4] = {};             // [h][b]
        for (int sc = 0; sc < SCHUNK; sc += 16) {
            for (int i = tid; i < 1024; i += NTHR) {
                int hh = i >> 4, sk = i & 15;
                int s = s0 + sc + sk;
                const float* wr = W_t + (size_t)(h0 + hh) * (2 * S);
                Ws[sk][hh] = wr[s] + 4.0f * wr[s + S];
            }
            for (int i = tid; i < 1024; i += NTHR) {
                int bb = i >> 4, sk = i & 15;
                int idx = bb * S + s0 + sc + sk;
                float v = g_xmp[idx] + g_xmp[B * S + idx]
                        + g_xmp[2 * B * S + idx] + g_xmp[3 * B * S + idx];
                Xs[sk][bb] = v * (1.0f / C);
            }
            __syncthreads();
#pragma unroll
            for (int sk = 0; sk < 16; ++sk) {
                float a_[4], w_[4];
#pragma unroll
                for (int i = 0; i < 4; ++i) a_[i] = Ws[sk][ty * 4 + i];
#pragma unroll
                for (int j = 0; j < 4; ++j) w_[j] = Xs[sk][tx * 4 + j];
#pragma unroll
                for (int i = 0; i < 4; ++i)
#pragma unroll
                    for (int j = 0; j < 4; ++j)
                        acc[i][j] += a_[i] * w_[j];
            }
            __syncthreads();
        }
        float* dst = g_fcp + (size_t)(blk & 15) * (H * B);
#pragma unroll
        for (int i = 0; i < 4; ++i) {
            float4 v = make_float4(acc[i][0], acc[i][1], acc[i][2], acc[i][3]);
            *reinterpret_cast<float4*>(&dst[(h0 + ty * 4 + i) * B + tx * 4]) = v;
        }
    }
    grid_barrier(ls);

    // ---------------- Phase 3: BN (biased var over batch) + ReLU -----------
    // block handles 4 h columns x all 64 b; writes out_fc [b][h].
    {
        const int b    = tid & 63;
        const int hl   = tid >> 6;
        const int h    = blk * 4 + hl;
        const int wid  = tid >> 5;
        const int lane = tid & 31;

        float v = b_t[h];
#pragma unroll
        for (int ks = 0; ks < KSPLIT; ++ks)
            v += g_fcp[(size_t)ks * (H * B) + h * B + b];

        float s = v;
#pragma unroll
        for (int o = 16; o; o >>= 1) s += __shfl_down_sync(0xffffffffu, s, o);
        if (!lane) sm[wid] = s;
        __syncthreads();
        const float mean = (sm[hl * 2] + sm[hl * 2 + 1]) * (1.0f / B);

        const float d = v - mean;
        float s2 = d * d;
#pragma unroll
        for (int o = 16; o; o >>= 1) s2 += __shfl_down_sync(0xffffffffu, s2, o);
        if (!lane) sm[8 + wid] = s2;
        __syncthreads();
        const float var = (sm[8 + hl * 2] + sm[8 + hl * 2 + 1]) * (1.0f / B);

        out_fc[b * H + h] =
            fmaxf(d * rsqrtf(var + 1e-5f) * gamma[h] + beta[h], 0.0f);
    }
    grid_barrier(ls);

    // ---------------- Phase 4: score = sigmoid(relu_fc @ W_l^T + b_l) ------
    // block = (b-quad, k-octet): 16 x 16 = 256 blocks. W_l rows reused by 4 b.
    {
        const int b0 = (blk >> 4) * 4;
        const int k0 = (blk & 15) * 8;
        float4* r4 = reinterpret_cast<float4*>(sm);     // [4][256] float4

        for (int i = tid; i < 4 * (H / 4); i += NTHR)
            r4[i] = reinterpret_cast<const float4*>(out_fc)
                        [(b0 + (i >> 8)) * (H / 4) + (i & 255)];
        __syncthreads();

        const int w = tid >> 5, lane = tid & 31;
        const int k = k0 + w;
        const float4* wl4 = reinterpret_cast<const float4*>(W_l + (size_t)k * H);
        float acc0 = 0.f, acc1 = 0.f, acc2 = 0.f, acc3 = 0.f;
#pragma unroll
        for (int j = 0; j < 8; ++j) {
            const float4 wv = __ldg(wl4 + lane + 32 * j);
            const float4 a0 = r4[0 * 256 + lane + 32 * j];
            const float4 a1 = r4[1 * 256 + lane + 32 * j];
            const float4 a2 = r4[2 * 256 + lane + 32 * j];
            const float4 a3 = r4[3 * 256 + lane + 32 * j];
            acc0 += a0.x * wv.x + a0.y * wv.y + a0.z * wv.z + a0.w * wv.w;
            acc1 += a1.x * wv.x + a1.y * wv.y + a1.z * wv.z + a1.w * wv.w;
            acc2 += a2.x * wv.x + a2.y * wv.y + a2.z * wv.z + a2.w * wv.w;
            acc3 += a3.x * wv.x + a3.y * wv.y + a3.z * wv.z + a3.w * wv.w;
        }
#pragma unroll
        for (int o = 16; o; o >>= 1) {
            acc0 += __shfl_down_sync(0xffffffffu, acc0, o);
            acc1 += __shfl_down_sync(0xffffffffu, acc1, o);
            acc2 += __shfl_down_sync(0xffffffffu, acc2, o);
            acc3 += __shfl_down_sync(0xffffffffu, acc3, o);
        }
        if (!lane) {
            const float bl = b_l[k];
            out_score[(b0 + 0) * K + k] = 1.0f / (1.0f + expf(-(acc0 + bl)));
            out_score[(b0 + 1) * K + k] = 1.0f / (1.0f + expf(-(acc1 + bl)));
            out_score[(b0 + 2) * K + k] = 1.0f / (1.0f + expf(-(acc2 + bl)));
            out_score[(b0 + 3) * K + k] = 1.0f / (1.0f + expf(-(acc3 + bl)));
        }
    }
    grid_barrier(ls);

    // ---------------- Phase 5: Q = score @ G_h, omega broadcast ------------
    // block = (b, n-slice of 64): 64 x 4 = 256 blocks.
    {
        const int b  = blk >> 2;
        const int n0 = (blk & 3) * 64;
        float* scsh  = sm;          // [128] score
        float* qpart = sm + 128;    // [4][64]
        float* qv    = sm + 384;    // [64]

        if (tid < K) scsh[tid] = out_score[b * K + tid];  // plain load (ours)
        __syncthreads();

        const int kh = tid >> 6;    // 0..3 -> k range [kh*32, kh*32+32)
        const int n  = tid & 63;
        float acc = 0.f;
#pragma unroll 8
        for (int j = 0; j < 32; ++j) {
            const int k = kh * 32 + j;
            acc += scsh[k] * __ldg(G_h + k * KN + n0 + n);
        }
        qpart[kh * 64 + n] = acc;
        __syncthreads();
        if (tid < 64)
            qv[tid] = qpart[tid] + qpart[64 + tid]
                    + qpart[128 + tid] + qpart[192 + tid];
        __syncthreads();

        // write 64 n rows x 200 a = 3200 float4
        float4* po = reinterpret_cast<float4*>(
            out_omega + (size_t)b * KN * A + (size_t)n0 * A);
#pragma unroll
        for (int it = 0; it < 13; ++it) {
            const int i4 = it * NTHR + tid;
            if (i4 < 64 * (A / 4)) {
                const float v = qv[i4 / (A / 4)];
                po[i4] = make_float4(v, v, v, v);
            }
        }
    }
}

// ---------------------------------------------------------------------------
extern "C" void kernel_launch(void* const* d_in, const int* in_sizes, int n_in,
                              void* d_out, int out_size) {
    const float* x     = (const float*)d_in[0];
    // d_in[1] omega_h, d_in[2] W_s1, d_in[3] W_s2: mathematically dead
    const float* W_t   = (const float*)d_in[4];
    const float* b_t   = (const float*)d_in[5];
    const float* gamma = (const float*)d_in[6];
    const float* beta  = (const float*)d_in[7];
    const float* W_l   = (const float*)d_in[8];
    const float* b_l   = (const float*)d_in[9];
    const float* G_h   = (const float*)d_in[10];

    float* out       = (float*)d_out;
    float* out_score = out;                    // [B, K]
    float* out_fc    = out + B * K;            // [B, H]
    float* out_omega = out + B * K + B * H;    // [B, KN, A]

    // Host-side attribute set (no allocation; graph-capture legal, idempotent).
    cudaFuncSetAttribute(ham_persistent,
                         cudaFuncAttributeMaxDynamicSharedMemorySize, SMEM_TOTAL);

    ham_persistent<<<NBLK, NTHR, SMEM_TOTAL>>>(x, W_t, b_t, gamma, beta,
                                               W_l, b_l, G_h,
                                               out_score, out_fc, out_omega);
}

// round 17
// speedup vs baseline: 1.2714x; 1.1807x over previous
#include <cuda_runtime.h>

#define B  64
#define C  512
#define S  768
#define K  128
#define KN 256
#define A  200
#define H  1024

#define NBLK 256
#define NTHR 256
#define KSPLIT 16
#define SCHUNK (S / KSPLIT)   // 48

// Scratch (device globals — no allocation allowed)
__device__ float g_xmp[4 * B * S];        // x-sum partials (4 c-quarters) [cq][b][s]
__device__ float g_fcp[KSPLIT * H * B];   // fc partials [ks][h][b]

// Grid-wide sense-reversing barrier (flat single atomic counter — measured
// faster than flag polling (R7), ticket stealing (R9), and 2-level tree (R13)).
__device__ int          g_bar_count = 0;
__device__ volatile int g_bar_sense = 0;

__device__ __forceinline__ void grid_barrier(int& ls) {
    __syncthreads();
    if (threadIdx.x == 0) {
        const int target = ls ^ 1;
        ls = target;
        __threadfence();
        if (atomicAdd(&g_bar_count, 1) == NBLK - 1) {
            atomicExch(&g_bar_count, 0);
            __threadfence();
            g_bar_sense = target;
        } else {
            while (g_bar_sense != target) { }
        }
        __threadfence();
    } else {
        ls ^= 1;
    }
    __syncthreads();
}

__device__ __forceinline__ void f4add(float4& a, const float4 v) {
    a.x += v.x; a.y += v.y; a.z += v.z; a.w += v.w;
}

// Streaming load for PURE INPUTS with zero reuse (phase-1 x only — R11 showed
// blanket no_allocate elsewhere regresses): L1 bypass + 256B L2 prefetch.
// This single change was worth 52 -> 45.5 us (R10).
__device__ __forceinline__ float4 ldg_stream(const float4* p) {
    float4 v;
    asm volatile("ld.global.nc.L1::no_allocate.L2::256B.v4.f32 {%0,%1,%2,%3}, [%4];"
                 : "=f"(v.x), "=f"(v.y), "=f"(v.z), "=f"(v.w)
                 : "l"(p));
    return v;
}

__global__ void __launch_bounds__(NTHR, 2)
ham_persistent(const float* __restrict__ x,
               const float* __restrict__ W_t,
               const float* __restrict__ b_t,
               const float* __restrict__ gamma,
               const float* __restrict__ beta,
               const float* __restrict__ W_l,
               const float* __restrict__ b_l,
               const float* __restrict__ G_h,
               float* __restrict__ out_score,
               float* __restrict__ out_fc,
               float* __restrict__ out_omega) {
    __shared__ __align__(16) float sm[4352];   // 17.4 KB, reused per phase

    const int blk = blockIdx.x;
    const int tid = threadIdx.x;
    int ls = g_bar_sense;                      // replay-safe sense init

    // ---------------- Phase 1: x-sum partials ------------------------------
    // block = (cq, b), 256 threads = 4 c-subgroups (32 rows) x 64 s-columns;
    // 2 rows/iter into 6 independent chains; L1-bypass streaming loads.
    {
        const int cq  = blk >> 6;              // 0..3
        const int b   = blk & 63;
        const int cs  = tid >> 6;              // 0..3
        const int s64 = tid & 63;

        const float4* p = reinterpret_cast<const float4*>(x)
                        + ((size_t)b * C + cq * 128 + cs * 32) * (S / 4);
        float4 a0 = make_float4(0.f, 0.f, 0.f, 0.f);
        float4 a1 = a0, a2 = a0, a3 = a0, a4 = a0, a5 = a0;
#pragma unroll 8
        for (int c = 0; c < 32; c += 2) {
            const float4* r0 = p + c * (S / 4);
            const float4* r1 = r0 + (S / 4);
            f4add(a0, ldg_stream(r0 + s64));
            f4add(a1, ldg_stream(r0 + s64 + 64));
            f4add(a2, ldg_stream(r0 + s64 + 128));
            f4add(a3, ldg_stream(r1 + s64));
            f4add(a4, ldg_stream(r1 + s64 + 64));
            f4add(a5, ldg_stream(r1 + s64 + 128));
        }
        f4add(a0, a3); f4add(a1, a4); f4add(a2, a5);
        float4* sm4 = reinterpret_cast<float4*>(sm);   // [4][192]
        sm4[cs * 192 + s64]       = a0;
        sm4[cs * 192 + s64 + 64]  = a1;
        sm4[cs * 192 + s64 + 128] = a2;
        __syncthreads();
        if (tid < 192) {
            float4 r = sm4[tid];
            f4add(r, sm4[192 + tid]);
            f4add(r, sm4[384 + tid]);
            f4add(r, sm4[576 + tid]);
            reinterpret_cast<float4*>(g_xmp)[(cq * B + b) * (S / 4) + tid] = r;
        }
    }
    grid_barrier(ls);

    // ---------------- Phase 2: fc partial GEMM -----------------------------
    // fc[b,h] = sum_s x_mean[b,s] * (W_t[h,s] + 4*W_t[h,s+S]); x_mean built
    // on the fly from the 4 c-quarter partials (L2-resident).
    // 256 blocks = 16 h-tiles x 16 s-splits of 48; 4x4 register tile.
    {
        float (*Xs)[64] = reinterpret_cast<float(*)[64]>(sm);          // [sk][b]
        float (*Ws)[64] = reinterpret_cast<float(*)[64]>(sm + 1024);   // [sk][h]
        const int h0 = (blk >> 4) * 64;
        const int s0 = (blk & 15) * SCHUNK;
        const int tx = tid & 15;          // b group
        const int ty = tid >> 4;          // h group

        float acc[4][4] = {};             // [h][b]
        for (int sc = 0; sc < SCHUNK; sc += 16) {
            for (int i = tid; i < 1024; i += NTHR) {
                int hh = i >> 4, sk = i & 15;
                int s = s0 + sc + sk;
                const float* wr = W_t + (size_t)(h0 + hh) * (2 * S);
                Ws[sk][hh] = wr[s] + 4.0f * wr[s + S];
            }
            for (int i = tid; i < 1024; i += NTHR) {
                int bb = i >> 4, sk = i & 15;
                int idx = bb * S + s0 + sc + sk;
                float v = g_xmp[idx] + g_xmp[B * S + idx]
                        + g_xmp[2 * B * S + idx] + g_xmp[3 * B * S + idx];
                Xs[sk][bb] = v * (1.0f / C);
            }
            __syncthreads();
#pragma unroll
            for (int sk = 0; sk < 16; ++sk) {
                float a_[4], w_[4];
#pragma unroll
                for (int i = 0; i < 4; ++i) a_[i] = Ws[sk][ty * 4 + i];
#pragma unroll
                for (int j = 0; j < 4; ++j) w_[j] = Xs[sk][tx * 4 + j];
#pragma unroll
                for (int i = 0; i < 4; ++i)
#pragma unroll
                    for (int j = 0; j < 4; ++j)
                        acc[i][j] += a_[i] * w_[j];
            }
            __syncthreads();
        }
        float* dst = g_fcp + (size_t)(blk & 15) * (H * B);
#pragma unroll
        for (int i = 0; i < 4; ++i) {
            float4 v = make_float4(acc[i][0], acc[i][1], acc[i][2], acc[i][3]);
            *reinterpret_cast<float4*>(&dst[(h0 + ty * 4 + i) * B + tx * 4]) = v;
        }
    }
    grid_barrier(ls);

    // ---------------- Phase 3: BN (biased var over batch) + ReLU -----------
    // block handles 4 h columns x all 64 b; writes out_fc [b][h].
    {
        const int b    = tid & 63;
        const int hl   = tid >> 6;
        const int h    = blk * 4 + hl;
        const int wid  = tid >> 5;
        const int lane = tid & 31;

        float v = b_t[h];
#pragma unroll
        for (int ks = 0; ks < KSPLIT; ++ks)
            v += g_fcp[(size_t)ks * (H * B) + h * B + b];

        float s = v;
#pragma unroll
        for (int o = 16; o; o >>= 1) s += __shfl_down_sync(0xffffffffu, s, o);
        if (!lane) sm[wid] = s;
        __syncthreads();
        const float mean = (sm[hl * 2] + sm[hl * 2 + 1]) * (1.0f / B);

        const float d = v - mean;
        float s2 = d * d;
#pragma unroll
        for (int o = 16; o; o >>= 1) s2 += __shfl_down_sync(0xffffffffu, s2, o);
        if (!lane) sm[8 + wid] = s2;
        __syncthreads();
        const float var = (sm[8 + hl * 2] + sm[8 + hl * 2 + 1]) * (1.0f / B);

        out_fc[b * H + h] =
            fmaxf(d * rsqrtf(var + 1e-5f) * gamma[h] + beta[h], 0.0f);
    }
    grid_barrier(ls);

    // ---------------- Phase 4: score = sigmoid(relu_fc @ W_l^T + b_l) ------
    // block = (b-quad, k-octet): 16 x 16 = 256 blocks. W_l rows reused by 4 b.
    {
        const int b0 = (blk >> 4) * 4;
        const int k0 = (blk & 15) * 8;
        float4* r4 = reinterpret_cast<float4*>(sm);     // [4][256] float4

        for (int i = tid; i < 4 * (H / 4); i += NTHR)
            r4[i] = reinterpret_cast<const float4*>(out_fc)
                        [(b0 + (i >> 8)) * (H / 4) + (i & 255)];
        __syncthreads();

        const int w = tid >> 5, lane = tid & 31;
        const int k = k0 + w;
        const float4* wl4 = reinterpret_cast<const float4*>(W_l + (size_t)k * H);
        float acc0 = 0.f, acc1 = 0.f, acc2 = 0.f, acc3 = 0.f;
#pragma unroll
        for (int j = 0; j < 8; ++j) {
            const float4 wv = __ldg(wl4 + lane + 32 * j);
            const float4 a0 = r4[0 * 256 + lane + 32 * j];
            const float4 a1 = r4[1 * 256 + lane + 32 * j];
            const float4 a2 = r4[2 * 256 + lane + 32 * j];
            const float4 a3 = r4[3 * 256 + lane + 32 * j];
            acc0 += a0.x * wv.x + a0.y * wv.y + a0.z * wv.z + a0.w * wv.w;
            acc1 += a1.x * wv.x + a1.y * wv.y + a1.z * wv.z + a1.w * wv.w;
            acc2 += a2.x * wv.x + a2.y * wv.y + a2.z * wv.z + a2.w * wv.w;
            acc3 += a3.x * wv.x + a3.y * wv.y + a3.z * wv.z + a3.w * wv.w;
        }
#pragma unroll
        for (int o = 16; o; o >>= 1) {
            acc0 += __shfl_down_sync(0xffffffffu, acc0, o);
            acc1 += __shfl_down_sync(0xffffffffu, acc1, o);
            acc2 += __shfl_down_sync(0xffffffffu, acc2, o);
            acc3 += __shfl_down_sync(0xffffffffu, acc3, o);
        }
        if (!lane) {
            const float bl = b_l[k];
            out_score[(b0 + 0) * K + k] = 1.0f / (1.0f + expf(-(acc0 + bl)));
            out_score[(b0 + 1) * K + k] = 1.0f / (1.0f + expf(-(acc1 + bl)));
            out_score[(b0 + 2) * K + k] = 1.0f / (1.0f + expf(-(acc2 + bl)));
            out_score[(b0 + 3) * K + k] = 1.0f / (1.0f + expf(-(acc3 + bl)));
        }
    }
    grid_barrier(ls);

    // ---------------- Phase 5: Q = score @ G_h, omega broadcast ------------
    // block = (b, n-slice of 64): 64 x 4 = 256 blocks.
    {
        const int b  = blk >> 2;
        const int n0 = (blk & 3) * 64;
        float* scsh  = sm;          // [128] score
        float* qpart = sm + 128;    // [4][64]
        float* qv    = sm + 384;    // [64]

        if (tid < K) scsh[tid] = out_score[b * K + tid];  // plain load (ours)
        __syncthreads();

        const int kh = tid >> 6;    // 0..3 -> k range [kh*32, kh*32+32)
        const int n  = tid & 63;
        float acc = 0.f;
#pragma unroll 8
        for (int j = 0; j < 32; ++j) {
            const int k = kh * 32 + j;
            acc += scsh[k] * __ldg(G_h + k * KN + n0 + n);
        }
        qpart[kh * 64 + n] = acc;
        __syncthreads();
        if (tid < 64)
            qv[tid] = qpart[tid] + qpart[64 + tid]
                    + qpart[128 + tid] + qpart[192 + tid];
        __syncthreads();

        // write 64 n rows x 200 a = 3200 float4
        float4* po = reinterpret_cast<float4*>(
            out_omega + (size_t)b * KN * A + (size_t)n0 * A);
#pragma unroll
        for (int it = 0; it < 13; ++it) {
            const int i4 = it * NTHR + tid;
            if (i4 < 64 * (A / 4)) {
                const float v = qv[i4 / (A / 4)];
                po[i4] = make_float4(v, v, v, v);
            }
        }
    }
}

// ---------------------------------------------------------------------------
extern "C" void kernel_launch(void* const* d_in, const int* in_sizes, int n_in,
                              void* d_out, int out_size) {
    const float* x     = (const float*)d_in[0];
    // d_in[1] omega_h, d_in[2] W_s1, d_in[3] W_s2: mathematically dead
    const float* W_t   = (const float*)d_in[4];
    const float* b_t   = (const float*)d_in[5];
    const float* gamma = (const float*)d_in[6];
    const float* beta  = (const float*)d_in[7];
    const float* W_l   = (const float*)d_in[8];
    const float* b_l   = (const float*)d_in[9];
    const float* G_h   = (const float*)d_in[10];

    float* out       = (float*)d_out;
    float* out_score = out;                    // [B, K]
    float* out_fc    = out + B * K;            // [B, H]
    float* out_omega = out + B * K + B * H;    // [B, KN, A]

    ham_persistent<<<NBLK, NTHR>>>(x, W_t, b_t, gamma, beta, W_l, b_l, G_h,
                                   out_score, out_fc, out_omega);
}